// round 11
// baseline (speedup 1.0000x reference)
#include <cuda_runtime.h>
#include <cuda_bf16.h>

// BumpX: out[b,l,f] = sum_g mask(g-f, aa[b,l,f]) * x[b,l,g] / sum_g mask(...)
// mask(d,a) = 1 - gg(arg), arg = (d^2 - a^2)/(6a+9).
//
// Round 11: R7 skeleton (2 threads/output tap-parity split — best so far) with
// the LUT reorganized to kill divergent-gather L1tex wavefronts:
//   * R7 gathered from ONE 8KB arg-indexed table -> ~26 distinct 128B lines
//     per warp-gather (aa uniform) -> ~104 wavefronts/warp -> ~3us of L1tex
//     serialization. That—not math—was the floor (R8/R10 probes confirm).
//   * Now: EIGHT per-d tables mask_d(a), 128 lerp segments in a, float2
//     {node, delta} entries -> 1KB per table = 8 cache lines -> ~8 lines per
//     gather, ~32 wf/warp. Index i=floor(a*128) and fraction computed ONCE,
//     shared by all 4 gathers; rcp(6a+9), a^2, per-tap arg FMAs all deleted.
//   * Tables baked at compile time (constexpr double-precision exact
//     reference formula incl. clamps). Lerp-in-a err <= ~2.5e-5 abs vs the
//     1e-3 gate. d=0's 0.5 double-count weight baked into its table.
//   * |d|<=7 window: dropped taps have mask <= 4e-11 (numerically identical
//     to dense fp32).
// Structure: h=0 handles d={0,2,4,6}, h=1 d={1,3,5,7}; shfl_xor combine;
// no smem/syncthreads; interior blocks drop boundary predicates.

#define BX_F    1024
#define BX_OPB  128
#define BX_TPB  256
#define BX_AN   128          // lerp segments in a, per d

// ---------- compile-time math (double precision) ----------
constexpr double BX_LN2 = 0.6931471805599453;

constexpr double bx_cexp(double x) {
    int n = (int)(x / BX_LN2 + (x >= 0.0 ? 0.5 : -0.5));
    double r = x - n * BX_LN2;
    double s = 1.0, term = 1.0;
    for (int k = 1; k <= 12; ++k) { term *= r / k; s += term; }
    double p = 1.0;
    int m = n < 0 ? -n : n;
    if (m > 1100) return n < 0 ? 0.0 : 1e308;
    for (int i = 0; i < m; ++i) p *= 2.0;
    return n < 0 ? s / p : s * p;
}
constexpr double bx_clog1p(double z) {          // z in (0, 1]
    double w = z / (z + 2.0);
    double w2 = w * w, s = 0.0, t = w;
    for (int k = 1; k <= 15; k += 2) { s += t / k; t *= w2; }
    return 2.0 * s;
}
constexpr double bx_csoftplus(double t) {
    double z = bx_cexp(t < 0.0 ? t : -t);
    double l = bx_clog1p(z);
    return (t > 0.0 ? t : 0.0) + l;
}
constexpr double bx_cmask_arg(double arg) {     // 1 - gg(arg), exact formula
    double u = bx_csoftplus(arg);        if (u < 1e-6) u = 1e-6;
    double v = bx_csoftplus(1.0 - arg);  if (v < 1e-6) v = 1e-6;
    double f1 = bx_cexp(-1.0 / u);
    double f2 = bx_cexp(-1.0 / v);
    if (f1 + f2 == 0.0) return 0.0;
    return f2 / (f1 + f2);
}
constexpr double bx_cmask_da(int d, double a) {
    double arg = ((double)(d * d) - a * a) / (6.0 * a + 9.0);
    return bx_cmask_arg(arg);
}

struct BxTab { float2 t[8][BX_AN]; };           // [d][i] = {m_i, m_{i+1}-m_i}; 8KB total, 1KB/d

constexpr BxTab bx_make_tab() {
    BxTab T{};
    for (int d = 0; d < 8; ++d) {
        double w = (d == 0) ? 0.5 : 1.0;        // bake d=0 double-count fix
        double prev = w * bx_cmask_da(d, 0.0);
        for (int i = 0; i < BX_AN; ++i) {
            double next = w * bx_cmask_da(d, (double)(i + 1) / BX_AN);
            T.t[d][i].x = (float)prev;
            T.t[d][i].y = (float)(next - prev);
            prev = next;
        }
    }
    return T;
}

__device__ const BxTab bx_tab = bx_make_tab();

// ---------- runtime ----------
__device__ __forceinline__ float bx_rcp(float x) {
    float r; asm("rcp.approx.ftz.f32 %0, %1;" : "=f"(r) : "f"(x)); return r;
}

template <bool INTERIOR>
__device__ __forceinline__ void bx_body(const float* __restrict__ x,
                                        const float* __restrict__ aa,
                                        float* __restrict__ out,
                                        int row, int fbase)
{
    const int o = (int)threadIdx.x >> 1;   // output within block
    const int h = (int)threadIdx.x & 1;    // tap-parity half

    const int f = fbase + o;
    const float* xr = x + row * BX_F;

    const float a = __ldg(aa + row * BX_F + f);

    // one shared lerp index/fraction for all 4 per-d tables
    const float t  = a * (float)BX_AN;
    const int   i  = min((int)t, BX_AN - 1);     // a in [0,1); guard anyway
    const float fr = t - (float)i;

    // 4 masks via tiny per-d gathers (1KB tables -> few L1 lines each)
    float mk[4];
    #pragma unroll
    for (int k = 0; k < 4; ++k) {
        const int d = 2 * k + h;
        float2 e = __ldg(&bx_tab.t[d][i]);
        mk[k] = fmaf(fr, e.y, e.x);
    }

    float ws = 0.0f;
    float dn = 0.0f;

    // h==0: d = 0,2,4,6 ; h==1: d = 1,3,5,7
    #pragma unroll
    for (int k = 0; k < 4; ++k) {
        const int d = 2 * k + h;
        if (INTERIOR) {
            ws = fmaf(mk[k], __ldg(xr + f - d) + __ldg(xr + f + d), ws);
            dn += mk[k];
        } else {
            const bool  lo = (f >= d);
            const bool  hi = (f + d < BX_F);
            const float xl = lo ? __ldg(xr + f - d) : 0.0f;
            const float xh = hi ? __ldg(xr + f + d) : 0.0f;
            ws = fmaf(mk[k], xl + xh, ws);
            dn = fmaf(mk[k], (float)((int)lo + (int)hi), dn);
        }
    }

    float den = INTERIOR ? (dn + dn) : dn;

    ws  += __shfl_xor_sync(0xFFFFFFFFu, ws,  1);
    den += __shfl_xor_sync(0xFFFFFFFFu, den, 1);

    if (h == 0)
        out[row * BX_F + f] = ws * bx_rcp(den);
}

__global__ __launch_bounds__(BX_TPB)
void BumpX_kernel(const float* __restrict__ x,
                  const float* __restrict__ aa,
                  float* __restrict__ out)
{
    const int row   = blockIdx.x >> 3;              // b*L + l
    const int chunk = blockIdx.x & 7;
    const int fbase = chunk * BX_OPB;

    if (chunk != 0 && chunk != 7)
        bx_body<true>(x, aa, out, row, fbase);
    else
        bx_body<false>(x, aa, out, row, fbase);
}

extern "C" void kernel_launch(void* const* d_in, const int* in_sizes, int n_in,
                              void* d_out, int out_size)
{
    const float* x  = (const float*)d_in[0];
    const float* aa = (const float*)d_in[1];
    float* out      = (float*)d_out;

    const int rows = out_size / BX_F;               // B*L = 128
    dim3 grid(rows * (BX_F / BX_OPB));              // 1024 blocks
    BumpX_kernel<<<grid, BX_TPB>>>(x, aa, out);
}

// round 12
// speedup vs baseline: 1.0556x; 1.0556x over previous
#include <cuda_runtime.h>
#include <cuda_bf16.h>

// BumpX: out[b,l,f] = sum_g mask(g-f, aa[b,l,f]) * x[b,l,g] / sum_g mask(...)
// mask(d,a) = 1 - gg(arg), arg = (d^2 - a^2)/(6a+9).
//
// Round 12: attack the cross-CTA L1tex queue spread (the one term R6..R11
// never touched; mask-path cost is saturated — MUFU mask (R6) and LUT mask
// (R7) tie at ~5.8us).
//   * per-thread global-load count: ~13 -> 2.  Each warp owns 16 consecutive
//     outputs; lane l loads ONE x value x[fw-8+l] (single coalesced LDG
//     covers the warp's whole +-7 window in registers). Taps come from
//     __shfl_sync dynamic-index — shuffle pipe, zero L1tex traffic.
//   * mask via the R6 MUFU path (ex2/lg2/rcp/tanh, all forced single-MUFU
//     via PTX): no LUT gathers at all.
//       Lu=lg2(1+2^(arg*log2e)), Lv=lg2(1+2^((1-arg)*log2e))
//       mask = 0.5 - 0.5*tanh(0.5*log2e*(Lu-Lv)*rcp(Lu*Lv))
//     tanh saturates to exactly +-1 -> mask exactly 0/1 like fp32 reference.
//   * |d|<=7 window: dropped taps have mask <= 4e-11 -> numerically
//     identical to dense fp32.
//   * 2 threads/output (h=0: d=0,2,4,6 with d=0 half-weighted; h=1: d=1,3,5,7),
//     shfl_xor combine; no smem, no barriers; interior chunks drop all
//     boundary predicates.

#define BX_F    1024
#define BX_OPB  128         // outputs per block (8 warps x 16 outputs)
#define BX_TPB  256
#define BX_L2E   1.4426950408889634f
#define BX_HL2E  0.7213475204444817f   // 0.5 * log2e

__device__ __forceinline__ float bx_ex2(float x) {
    float r; asm("ex2.approx.ftz.f32 %0, %1;" : "=f"(r) : "f"(x)); return r;
}
__device__ __forceinline__ float bx_lg2(float x) {
    float r; asm("lg2.approx.ftz.f32 %0, %1;" : "=f"(r) : "f"(x)); return r;
}
__device__ __forceinline__ float bx_rcp(float x) {
    float r; asm("rcp.approx.ftz.f32 %0, %1;" : "=f"(r) : "f"(x)); return r;
}
__device__ __forceinline__ float bx_tanh(float x) {
    float r; asm("tanh.approx.f32 %0, %1;" : "=f"(r) : "f"(x)); return r;
}

__device__ __forceinline__ float bx_mask(float a1) {
    // a1 = arg * log2e
    float Lu = bx_lg2(1.0f + bx_ex2(a1));
    float Lv = bx_lg2(1.0f + bx_ex2(BX_L2E - a1));
    float q  = (Lu - Lv) * bx_rcp(Lu * Lv);
    return fmaf(-0.5f, bx_tanh(BX_HL2E * q), 0.5f);
}

template <bool INTERIOR>
__device__ __forceinline__ void bx_body(const float* __restrict__ x,
                                        const float* __restrict__ aa,
                                        float* __restrict__ out,
                                        int row, int fbase)
{
    const int warp = (int)threadIdx.x >> 5;       // 0..7
    const int lane = (int)threadIdx.x & 31;
    const int o    = lane >> 1;                   // output within warp: 0..15
    const int h    = lane & 1;                    // tap-parity half

    const int fw = fbase + warp * 16;             // warp's first output
    const int f  = fw + o;

    const float* xr = x + row * BX_F;

    // one x load per lane covers the warp's whole window [fw-8, fw+23]
    float xv;
    {
        const int g = fw - 8 + lane;
        if (INTERIOR) {
            xv = __ldg(xr + g);
        } else {
            xv = (g >= 0 && g < BX_F) ? __ldg(xr + g) : 0.0f;
        }
    }

    const float a        = __ldg(aa + row * BX_F + f);
    const float inv_den2 = BX_L2E * bx_rcp(fmaf(6.0f, a, 9.0f));
    const float c02      = a * a * inv_den2;      // (a^2/(6a+9)) * log2e

    float ws = 0.0f;
    float dn = 0.0f;

    // h==0: d = 0,2,4,6 (d=0 half-weighted) ; h==1: d = 1,3,5,7
    #pragma unroll
    for (int k = 0; k < 4; ++k) {
        const int   d  = 2 * k + h;
        const float w  = (d == 0) ? 0.5f : 1.0f;
        const float a1 = fmaf((float)(d * d), inv_den2, -c02);
        const float mw = w * bx_mask(a1);

        // taps via register shuffle: lane (o +- d) + 8 holds x[f +- d]
        const float xm = __shfl_sync(0xFFFFFFFFu, xv, (o - d) + 8);
        const float xp = __shfl_sync(0xFFFFFFFFu, xv, (o + d) + 8);

        ws = fmaf(mw, xm + xp, ws);
        if (INTERIOR) {
            dn += mw;
        } else {
            const float cnt = (float)((f >= d) + (f + d < BX_F));
            dn = fmaf(mw, cnt, dn);
        }
    }

    float den = INTERIOR ? (dn + dn) : dn;

    // combine tap-parity halves
    ws  += __shfl_xor_sync(0xFFFFFFFFu, ws,  1);
    den += __shfl_xor_sync(0xFFFFFFFFu, den, 1);

    if (h == 0)
        out[row * BX_F + f] = ws * bx_rcp(den);
}

__global__ __launch_bounds__(BX_TPB)
void BumpX_kernel(const float* __restrict__ x,
                  const float* __restrict__ aa,
                  float* __restrict__ out)
{
    const int row   = blockIdx.x >> 3;            // b*L + l
    const int chunk = blockIdx.x & 7;
    const int fbase = chunk * BX_OPB;

    if (chunk != 0 && chunk != 7)
        bx_body<true>(x, aa, out, row, fbase);
    else
        bx_body<false>(x, aa, out, row, fbase);
}

extern "C" void kernel_launch(void* const* d_in, const int* in_sizes, int n_in,
                              void* d_out, int out_size)
{
    const float* x  = (const float*)d_in[0];
    const float* aa = (const float*)d_in[1];
    float* out      = (float*)d_out;

    const int rows = out_size / BX_F;             // B*L = 128
    dim3 grid(rows * (BX_F / BX_OPB));            // 1024 blocks
    BumpX_kernel<<<grid, BX_TPB>>>(x, aa, out);
}

// round 13
// speedup vs baseline: 1.1633x; 1.1020x over previous
#include <cuda_runtime.h>
#include <cuda_bf16.h>

// BumpX: out[b,l,f] = sum_g mask(g-f, aa[b,l,f]) * x[b,l,g] / sum_g mask(...)
// mask(d,a) = 1 - gg(arg), arg = (d^2 - a^2)/(6a+9).
//
// Round 13: R12 load structure (warp-coalesced single x LDG + shuffle taps,
// 2 LDG/thread — fewest of all variants) with the mask's tanh PRE-ACTIVATION
// replaced by one shared compile-time polynomial:
//   mask = 0.5 - 0.5*tanh(p),  p(arg) = 0.5*(1/v - 1/u),
//   u = clamp(softplus(arg)), v = clamp(softplus(1-arg)).
// p is smooth and e^x-like on arg in [-0.07, 5.45] (max ~43). Degree-10
// Chebyshev-node interpolation (constexpr double, exact reference formula
// incl. clamps) gives |dp| <~ 7e-5 -> mask abs err <~ 4e-5 (tanh slope <=
// 0.5) vs the 1e-3 gate. Runtime per mask: 10 FMA Horner + ONE MUFU.TANH
// (was 6 MUFU + glue): -160 SMSP-cycles/warp of MUFU rt pressure, shorter
// dependency chains. tanh saturates to exactly +-1 -> mask exactly 0/1,
// matching fp32-reference overflow behavior.
//   * |d|<=7 window: dropped taps have mask <= 4e-11.
//   * 2 threads/output (h=0: d=0,2,4,6, d=0 half-weighted; h=1: d=1,3,5,7),
//     shfl_xor combine; no smem/barriers; interior chunks drop predicates.

#define BX_F    1024
#define BX_OPB  128         // outputs per block (8 warps x 16 outputs)
#define BX_TPB  256
#define BX_DEG  10

// poly domain in arg
constexpr double BX_ALO = -0.07;
constexpr double BX_AHI =  5.45;

// ---------- compile-time math (double precision) ----------
constexpr double BX_LN2 = 0.6931471805599453;
constexpr double BX_PI  = 3.14159265358979323846;

constexpr double bx_cexp(double x) {
    int n = (int)(x / BX_LN2 + (x >= 0.0 ? 0.5 : -0.5));
    double r = x - n * BX_LN2;
    double s = 1.0, term = 1.0;
    for (int k = 1; k <= 12; ++k) { term *= r / k; s += term; }
    double p = 1.0;
    int m = n < 0 ? -n : n;
    if (m > 1100) return n < 0 ? 0.0 : 1e308;
    for (int i = 0; i < m; ++i) p *= 2.0;
    return n < 0 ? s / p : s * p;
}
constexpr double bx_clog1p(double z) {          // z in (0, 1]
    double w = z / (z + 2.0);
    double w2 = w * w, s = 0.0, t = w;
    for (int k = 1; k <= 15; k += 2) { s += t / k; t *= w2; }
    return 2.0 * s;
}
constexpr double bx_csoftplus(double t) {
    double z = bx_cexp(t < 0.0 ? t : -t);
    double l = bx_clog1p(z);
    return (t > 0.0 ? t : 0.0) + l;
}
constexpr double bx_ccos(double x) {            // |x| <= pi
    double x2 = x * x, s = 1.0, t = 1.0;
    for (int k = 1; k <= 24; ++k) { t *= -x2 / ((2.0*k - 1.0) * (2.0*k)); s += t; }
    return s;
}
// tanh pre-activation of the exact reference mask (clamps included)
constexpr double bx_cp(double arg) {
    double u = bx_csoftplus(arg);        if (u < 1e-6) u = 1e-6;
    double v = bx_csoftplus(1.0 - arg);  if (v < 1e-6) v = 1e-6;
    return 0.5 * (1.0 / v - 1.0 / u);
}

// Degree-BX_DEG interpolation of p at Chebyshev nodes on [BX_ALO, BX_AHI],
// in normalized variable z = (arg - mid)/half; Lagrange -> monomial (double).
struct BxPoly { float c[BX_DEG + 1]; };

constexpr BxPoly bx_make_poly() {
    constexpr double mid  = 0.5 * (BX_AHI + BX_ALO);
    constexpr double half = 0.5 * (BX_AHI - BX_ALO);
    double zj[BX_DEG + 1] = {};
    double yj[BX_DEG + 1] = {};
    for (int j = 0; j <= BX_DEG; ++j) {
        double th = BX_PI * (2.0 * j + 1.0) / (2.0 * (BX_DEG + 1));
        zj[j] = bx_ccos(th);
        yj[j] = bx_cp(mid + half * zj[j]);
    }
    double C[BX_DEG + 1] = {};
    for (int j = 0; j <= BX_DEG; ++j) {
        double num[BX_DEG + 2] = {};
        num[0] = 1.0;
        int deg = 0;
        double den = 1.0;
        for (int k = 0; k <= BX_DEG; ++k) {
            if (k == j) continue;
            double r = zj[k];
            for (int i = deg + 1; i >= 1; --i) num[i] = num[i - 1] - r * num[i];
            num[0] = -r * num[0];
            ++deg;
            den *= (zj[j] - r);
        }
        double scale = yj[j] / den;
        for (int i = 0; i <= BX_DEG; ++i) C[i] += scale * num[i];
    }
    BxPoly P{};
    for (int i = 0; i <= BX_DEG; ++i) P.c[i] = (float)C[i];
    return P;
}

__constant__ BxPoly bx_poly = bx_make_poly();

// z = arg * BX_ZS1 + BX_ZS0
#define BX_ZS1 (float)(2.0 / (BX_AHI - BX_ALO))
#define BX_ZS0 (float)(-(BX_AHI + BX_ALO) / (BX_AHI - BX_ALO))

// ---------- runtime ----------
__device__ __forceinline__ float bx_rcp(float x) {
    float r; asm("rcp.approx.ftz.f32 %0, %1;" : "=f"(r) : "f"(x)); return r;
}
__device__ __forceinline__ float bx_tanh(float x) {
    float r; asm("tanh.approx.f32 %0, %1;" : "=f"(r) : "f"(x)); return r;
}

// mask from normalized poly argument z (4 independent Horner chains/thread)
__device__ __forceinline__ float bx_mask_z(float z) {
    float p = bx_poly.c[BX_DEG];
    #pragma unroll
    for (int i = BX_DEG - 1; i >= 0; --i)
        p = fmaf(p, z, bx_poly.c[i]);
    return fmaf(-0.5f, bx_tanh(p), 0.5f);
}

template <bool INTERIOR>
__device__ __forceinline__ void bx_body(const float* __restrict__ x,
                                        const float* __restrict__ aa,
                                        float* __restrict__ out,
                                        int row, int fbase)
{
    const int warp = (int)threadIdx.x >> 5;       // 0..7
    const int lane = (int)threadIdx.x & 31;
    const int o    = lane >> 1;                   // output within warp: 0..15
    const int h    = lane & 1;                    // tap-parity half

    const int fw = fbase + warp * 16;             // warp's first output
    const int f  = fw + o;

    const float* xr = x + row * BX_F;

    // one x load per lane covers the warp's whole window [fw-8, fw+23]
    float xv;
    {
        const int g = fw - 8 + lane;
        if (INTERIOR) {
            xv = __ldg(xr + g);
        } else {
            xv = (g >= 0 && g < BX_F) ? __ldg(xr + g) : 0.0f;
        }
    }

    const float a = __ldg(aa + row * BX_F + f);

    // z(d) = (d^2 - a^2) * inv_den * ZS1 + ZS0 = d^2 * id2 + c0
    const float id2 = BX_ZS1 * bx_rcp(fmaf(6.0f, a, 9.0f));
    const float c0  = fmaf(-a * a, id2, BX_ZS0);

    float ws = 0.0f;
    float dn = 0.0f;

    // h==0: d = 0,2,4,6 (d=0 half-weighted) ; h==1: d = 1,3,5,7
    #pragma unroll
    for (int k = 0; k < 4; ++k) {
        const int   d  = 2 * k + h;
        const float w  = (d == 0) ? 0.5f : 1.0f;
        const float z  = fmaf((float)(d * d), id2, c0);
        const float mw = w * bx_mask_z(z);

        // taps via register shuffle: lane (o +- d) + 8 holds x[f +- d]
        const float xm = __shfl_sync(0xFFFFFFFFu, xv, (o - d) + 8);
        const float xp = __shfl_sync(0xFFFFFFFFu, xv, (o + d) + 8);

        ws = fmaf(mw, xm + xp, ws);
        if (INTERIOR) {
            dn += mw;
        } else {
            const float cnt = (float)((f >= d) + (f + d < BX_F));
            dn = fmaf(mw, cnt, dn);
        }
    }

    float den = INTERIOR ? (dn + dn) : dn;

    // combine tap-parity halves
    ws  += __shfl_xor_sync(0xFFFFFFFFu, ws,  1);
    den += __shfl_xor_sync(0xFFFFFFFFu, den, 1);

    if (h == 0)
        out[row * BX_F + f] = ws * bx_rcp(den);
}

__global__ __launch_bounds__(BX_TPB)
void BumpX_kernel(const float* __restrict__ x,
                  const float* __restrict__ aa,
                  float* __restrict__ out)
{
    const int row   = blockIdx.x >> 3;            // b*L + l
    const int chunk = blockIdx.x & 7;
    const int fbase = chunk * BX_OPB;

    if (chunk != 0 && chunk != 7)
        bx_body<true>(x, aa, out, row, fbase);
    else
        bx_body<false>(x, aa, out, row, fbase);
}

extern "C" void kernel_launch(void* const* d_in, const int* in_sizes, int n_in,
                              void* d_out, int out_size)
{
    const float* x  = (const float*)d_in[0];
    const float* aa = (const float*)d_in[1];
    float* out      = (float*)d_out;

    const int rows = out_size / BX_F;             // B*L = 128
    dim3 grid(rows * (BX_F / BX_OPB));            // 1024 blocks
    BumpX_kernel<<<grid, BX_TPB>>>(x, aa, out);
}

// round 14
// speedup vs baseline: 1.1813x; 1.0155x over previous
#include <cuda_runtime.h>
#include <cuda_bf16.h>

// BumpX: out[b,l,f] = sum_g mask(g-f, aa[b,l,f]) * x[b,l,g] / sum_g mask(...)
// mask(d,a) = 1 - gg(arg), arg = (d^2 - a^2)/(6a+9).
//
// Round 14: R13 (best: warp-coalesced x load + shuffle taps, deg-10 Chebyshev
// poly of the tanh pre-activation, one MUFU.TANH per mask) with the FOUR
// scalar Horner chains packed into TWO f32x2 chains (PTX fma.rn.f32x2 ->
// SASS FFMA2): 40 FFMA -> 20 FFMA2 (+2 packs, +2 unpacks). Coefficients are
// compile-time-packed (c,c) 64-bit constants. Per-element rounding is
// IEEE-rn -> bitwise identical to R13's math.
//   mask = 0.5 - 0.5*tanh(p(arg)), p = 0.5*(1/v - 1/u),
//   u = clamp(softplus(arg)), v = clamp(softplus(1-arg));
//   p interpolated at deg-10 Chebyshev nodes on arg in [-0.07, 5.45]
//   (constexpr double, exact reference formula incl. clamps);
//   |dp| <~ 7e-5 -> mask abs err <~ 4e-5 vs 1e-3 gate (measured 3.6e-6).
//   tanh saturates to exactly +-1 -> mask exactly 0/1 (fp32-ref overflow).
//   |d|<=7 window: dropped taps have mask <= 4e-11.
// Structure: 2 threads/output (h=0: d=0,2,4,6, d=0 half-weighted;
// h=1: d=1,3,5,7), shfl_xor combine; no smem/barriers; interior chunks
// drop boundary predicates.

#define BX_F    1024
#define BX_OPB  128         // outputs per block (8 warps x 16 outputs)
#define BX_TPB  256
#define BX_DEG  10

constexpr double BX_ALO = -0.07;
constexpr double BX_AHI =  5.45;

// ---------- compile-time math (double precision) ----------
constexpr double BX_LN2 = 0.6931471805599453;
constexpr double BX_PI  = 3.14159265358979323846;

constexpr double bx_cexp(double x) {
    int n = (int)(x / BX_LN2 + (x >= 0.0 ? 0.5 : -0.5));
    double r = x - n * BX_LN2;
    double s = 1.0, term = 1.0;
    for (int k = 1; k <= 12; ++k) { term *= r / k; s += term; }
    double p = 1.0;
    int m = n < 0 ? -n : n;
    if (m > 1100) return n < 0 ? 0.0 : 1e308;
    for (int i = 0; i < m; ++i) p *= 2.0;
    return n < 0 ? s / p : s * p;
}
constexpr double bx_clog1p(double z) {          // z in (0, 1]
    double w = z / (z + 2.0);
    double w2 = w * w, s = 0.0, t = w;
    for (int k = 1; k <= 15; k += 2) { s += t / k; t *= w2; }
    return 2.0 * s;
}
constexpr double bx_csoftplus(double t) {
    double z = bx_cexp(t < 0.0 ? t : -t);
    double l = bx_clog1p(z);
    return (t > 0.0 ? t : 0.0) + l;
}
constexpr double bx_ccos(double x) {            // |x| <= pi
    double x2 = x * x, s = 1.0, t = 1.0;
    for (int k = 1; k <= 24; ++k) { t *= -x2 / ((2.0*k - 1.0) * (2.0*k)); s += t; }
    return s;
}
constexpr double bx_cp(double arg) {            // tanh pre-activation, exact
    double u = bx_csoftplus(arg);        if (u < 1e-6) u = 1e-6;
    double v = bx_csoftplus(1.0 - arg);  if (v < 1e-6) v = 1e-6;
    return 0.5 * (1.0 / v - 1.0 / u);
}

struct BxPolyPk { unsigned long long c[BX_DEG + 1]; };   // (c_i, c_i) packed

constexpr BxPolyPk bx_make_poly() {
    constexpr double mid  = 0.5 * (BX_AHI + BX_ALO);
    constexpr double half = 0.5 * (BX_AHI - BX_ALO);
    double zj[BX_DEG + 1] = {};
    double yj[BX_DEG + 1] = {};
    for (int j = 0; j <= BX_DEG; ++j) {
        double th = BX_PI * (2.0 * j + 1.0) / (2.0 * (BX_DEG + 1));
        zj[j] = bx_ccos(th);
        yj[j] = bx_cp(mid + half * zj[j]);
    }
    double C[BX_DEG + 1] = {};
    for (int j = 0; j <= BX_DEG; ++j) {
        double num[BX_DEG + 2] = {};
        num[0] = 1.0;
        int deg = 0;
        double den = 1.0;
        for (int k = 0; k <= BX_DEG; ++k) {
            if (k == j) continue;
            double r = zj[k];
            for (int i = deg + 1; i >= 1; --i) num[i] = num[i - 1] - r * num[i];
            num[0] = -r * num[0];
            ++deg;
            den *= (zj[j] - r);
        }
        double scale = yj[j] / den;
        for (int i = 0; i <= BX_DEG; ++i) C[i] += scale * num[i];
    }
    BxPolyPk P{};
    for (int i = 0; i <= BX_DEG; ++i) {
        float cf = (float)C[i];
        unsigned int b = __builtin_bit_cast(unsigned int, cf);
        P.c[i] = ((unsigned long long)b << 32) | b;
    }
    return P;
}

__constant__ BxPolyPk bx_poly = bx_make_poly();

// z = arg * BX_ZS1 + BX_ZS0  (normalize to [-1,1])
#define BX_ZS1 (float)(2.0 / (BX_AHI - BX_ALO))
#define BX_ZS0 (float)(-(BX_AHI + BX_ALO) / (BX_AHI - BX_ALO))

// ---------- runtime ----------
__device__ __forceinline__ float bx_rcp(float x) {
    float r; asm("rcp.approx.ftz.f32 %0, %1;" : "=f"(r) : "f"(x)); return r;
}
__device__ __forceinline__ float bx_tanh(float x) {
    float r; asm("tanh.approx.f32 %0, %1;" : "=f"(r) : "f"(x)); return r;
}
__device__ __forceinline__ unsigned long long bx_pack2(float lo, float hi) {
    unsigned long long r;
    asm("mov.b64 %0, {%1, %2};" : "=l"(r)
        : "r"(__float_as_uint(lo)), "r"(__float_as_uint(hi)));
    return r;
}
__device__ __forceinline__ void bx_unpack2(unsigned long long v, float& lo, float& hi) {
    unsigned int a, b;
    asm("mov.b64 {%0, %1}, %2;" : "=r"(a), "=r"(b) : "l"(v));
    lo = __uint_as_float(a);
    hi = __uint_as_float(b);
}
__device__ __forceinline__ unsigned long long bx_fma2(unsigned long long a,
                                                      unsigned long long b,
                                                      unsigned long long c) {
    unsigned long long r;
    asm("fma.rn.f32x2 %0, %1, %2, %3;" : "=l"(r) : "l"(a), "l"(b), "l"(c));
    return r;
}

template <bool INTERIOR>
__device__ __forceinline__ void bx_body(const float* __restrict__ x,
                                        const float* __restrict__ aa,
                                        float* __restrict__ out,
                                        int row, int fbase)
{
    const int warp = (int)threadIdx.x >> 5;       // 0..7
    const int lane = (int)threadIdx.x & 31;
    const int o    = lane >> 1;                   // output within warp: 0..15
    const int h    = lane & 1;                    // tap-parity half

    const int fw = fbase + warp * 16;             // warp's first output
    const int f  = fw + o;

    const float* xr = x + row * BX_F;

    // one x load per lane covers the warp's whole window [fw-8, fw+23]
    float xv;
    {
        const int g = fw - 8 + lane;
        if (INTERIOR) {
            xv = __ldg(xr + g);
        } else {
            xv = (g >= 0 && g < BX_F) ? __ldg(xr + g) : 0.0f;
        }
    }

    const float a = __ldg(aa + row * BX_F + f);

    // z(d) = d^2 * id2 + c0   (normalized poly argument)
    const float id2 = BX_ZS1 * bx_rcp(fmaf(6.0f, a, 9.0f));
    const float c0  = fmaf(-a * a, id2, BX_ZS0);

    // the 4 taps of this parity half: d_k = 2k + h
    float z[4];
    #pragma unroll
    for (int k = 0; k < 4; ++k) {
        const int d = 2 * k + h;
        z[k] = fmaf((float)(d * d), id2, c0);
    }

    // two packed Horner chains: (z0,z1) and (z2,z3)
    unsigned long long z01 = bx_pack2(z[0], z[1]);
    unsigned long long z23 = bx_pack2(z[2], z[3]);
    unsigned long long p01 = bx_poly.c[BX_DEG];
    unsigned long long p23 = p01;
    #pragma unroll
    for (int i = BX_DEG - 1; i >= 0; --i) {
        const unsigned long long ci = bx_poly.c[i];
        p01 = bx_fma2(p01, z01, ci);
        p23 = bx_fma2(p23, z23, ci);
    }

    float p[4];
    bx_unpack2(p01, p[0], p[1]);
    bx_unpack2(p23, p[2], p[3]);

    float ws = 0.0f;
    float dn = 0.0f;

    // h==0: d = 0,2,4,6 (d=0 half-weighted) ; h==1: d = 1,3,5,7
    #pragma unroll
    for (int k = 0; k < 4; ++k) {
        const int   d  = 2 * k + h;
        const float w  = (d == 0) ? 0.5f : 1.0f;
        const float m  = fmaf(-0.5f, bx_tanh(p[k]), 0.5f);
        const float mw = w * m;

        // taps via register shuffle: lane (o +- d) + 8 holds x[f +- d]
        const float xm = __shfl_sync(0xFFFFFFFFu, xv, (o - d) + 8);
        const float xp = __shfl_sync(0xFFFFFFFFu, xv, (o + d) + 8);

        ws = fmaf(mw, xm + xp, ws);
        if (INTERIOR) {
            dn += mw;
        } else {
            const float cnt = (float)((f >= d) + (f + d < BX_F));
            dn = fmaf(mw, cnt, dn);
        }
    }

    float den = INTERIOR ? (dn + dn) : dn;

    // combine tap-parity halves
    ws  += __shfl_xor_sync(0xFFFFFFFFu, ws,  1);
    den += __shfl_xor_sync(0xFFFFFFFFu, den, 1);

    if (h == 0)
        out[row * BX_F + f] = ws * bx_rcp(den);
}

__global__ __launch_bounds__(BX_TPB)
void BumpX_kernel(const float* __restrict__ x,
                  const float* __restrict__ aa,
                  float* __restrict__ out)
{
    const int row   = blockIdx.x >> 3;            // b*L + l
    const int chunk = blockIdx.x & 7;
    const int fbase = chunk * BX_OPB;

    if (chunk != 0 && chunk != 7)
        bx_body<true>(x, aa, out, row, fbase);
    else
        bx_body<false>(x, aa, out, row, fbase);
}

extern "C" void kernel_launch(void* const* d_in, const int* in_sizes, int n_in,
                              void* d_out, int out_size)
{
    const float* x  = (const float*)d_in[0];
    const float* aa = (const float*)d_in[1];
    float* out      = (float*)d_out;

    const int rows = out_size / BX_F;             // B*L = 128
    dim3 grid(rows * (BX_F / BX_OPB));            // 1024 blocks
    BumpX_kernel<<<grid, BX_TPB>>>(x, aa, out);
}